// round 5
// baseline (speedup 1.0000x reference)
#include <cuda_runtime.h>
#include <math.h>

#define B_    256
#define M_    64
#define DSLOT 126
#define D_    128
#define C_    62
#define KP_   32
#define BETA_ 4.0f
#define XYW_  0.5f
#define TOPP_ 0.9f

// A column (c,k) can contribute a nonzero fp32 sim only if exp(-4*dist2) >= 2^-149,
// i.e. dist2 < 26. Since dist2 >= (||c||-||f||)^2 and ||f|| <= sqrt(1.25)+eps < 1.13,
// ||c||^2 >= 40 gives (6.324-1.13)^2 = 26.98 > 26 -> sim == 0.0f exactly for every
// (b,m), identical to the fp32 reference. If no column of class c survives,
// scores[:,c] == 0 exactly and out[:,c] = alpha*base[:,c].
#define C2_SURV 40.0f

#define NT 256   // == B_ : thread tid handles row b = tid on the fast path

__global__ __launch_bounds__(NT)
void k_fused(const float* __restrict__ base, const float* __restrict__ S,
             const float* __restrict__ XY, const float* __restrict__ P,
             const float* __restrict__ mask, const float* __restrict__ cen,
             const float* __restrict__ psi, const float* __restrict__ ap,
             float* __restrict__ out)
{
    const int c    = blockIdx.x;           // one block per class
    const int tid  = threadIdx.x;
    const int warp = tid >> 5;             // 0..7
    const int lane = tid & 31;

    __shared__ float sh_c2[KP_];
    __shared__ int   sh_any;               // nonzero iff any column survives

    if (tid == 0) sh_any = 0;

    // ---- issue ALL loads first: base row, alpha scalar, 4x LDG.128 of centers ----
    const float my_base = base[tid * C_ + c];           // b = tid (NT == B_)
    const float ap0 = ap[0];

    const int   col  = warp * 4 + (lane >> 3);          // warp owns cols 4w..4w+3
    const int   sub  = lane & 7;                        // 8 lanes per column
    const float4* cp = (const float4*)(cen + (size_t)(c * KP_ + col) * D_);
    float4 v0 = cp[sub +  0];
    float4 v1 = cp[sub +  8];
    float4 v2 = cp[sub + 16];
    float4 v3 = cp[sub + 24];

    // overlap MUFU sigmoid + fast-path FFMA with the loads above
    const float alpha   = 1.f / (1.f + expf(-ap0));
    const float fastval = alpha * my_base;

    float s = v0.x*v0.x + v0.y*v0.y + v0.z*v0.z + v0.w*v0.w
            + v1.x*v1.x + v1.y*v1.y + v1.z*v1.z + v1.w*v1.w
            + v2.x*v2.x + v2.y*v2.y + v2.z*v2.z + v2.w*v2.w
            + v3.x*v3.x + v3.y*v3.y + v3.z*v3.z + v3.w*v3.w;
    // reduce within each aligned 8-lane group
    s += __shfl_xor_sync(0xffffffffu, s, 4);
    s += __shfl_xor_sync(0xffffffffu, s, 2);
    s += __shfl_xor_sync(0xffffffffu, s, 1);
    if (sub == 0) {
        sh_c2[col] = s;                    // needed only by the fallback path
        if (s < C2_SURV) atomicOr(&sh_any, 1);   // exceptional: normally never fires
    }
    __syncthreads();

    if (sh_any == 0) {
        // Fast path: every sim term for class c underflows to exactly 0.0f.
        out[tid * C_ + c] = fastval;
        return;
    }

    // ---------------- survivor fallback (correct; normally never taken) ----------------
    __shared__ float sh_w[KP_];          // softmax(psi[c,:])
    __shared__ float sh_v[M_], sh_vs[M_];
    __shared__ unsigned char sh_act[M_];
    __shared__ int   sh_k;
    __shared__ float sh_score;

    if (tid == 0) {
        float mx = -1e30f;
        #pragma unroll
        for (int k = 0; k < KP_; k++) mx = fmaxf(mx, psi[c * KP_ + k]);
        float e[KP_], ssum = 0.f;
        #pragma unroll
        for (int k = 0; k < KP_; k++) { e[k] = expf(psi[c * KP_ + k] - mx); ssum += e[k]; }
        float inv = 1.f / ssum;
        #pragma unroll
        for (int k = 0; k < KP_; k++) sh_w[k] = e[k] * inv;
    }
    __syncthreads();

    for (int b = 0; b < B_; b++) {
        // --- top-p: k and active set for batch b (threads 0..63) ---
        if (tid < M_) {
            int m = tid;
            sh_v[m] = P[b * M_ + m] * mask[b * M_ + m];
        }
        __syncthreads();
        if (tid < M_) {
            int m = tid;
            float val = sh_v[m];
            int rank = 0; float tot = 0.f;
            #pragma unroll
            for (int j = 0; j < M_; j++) {
                float o = sh_v[j];
                tot += o;
                if (o > val || (o == val && j < m)) rank++;   // stable descending
            }
            sh_vs[rank] = val;
            __syncthreads();
            if (m == 0) {
                float thr = TOPP_ * (tot + 1e-8f);
                float cs = 0.f; int kk = 0;
                #pragma unroll
                for (int j = 0; j < M_; j++) { cs += sh_vs[j]; if (cs <= thr) kk++; }
                if (kk < 1) kk = 1;
                sh_k = kk;
                sh_score = 0.f;
            }
            __syncthreads();
            sh_act[m] = (rank < sh_k) ? 1 : 0;
        } else {
            __syncthreads();  // match the __syncthreads inside the tid<M_ branch
            __syncthreads();
        }
        __syncthreads();

        // --- accumulate sum over (active m) x (surviving cols) of sim * w ---
        float acc = 0.f;
        for (int pr = tid; pr < M_ * KP_; pr += NT) {
            int m = pr >> 5;
            int k = pr & 31;
            if (!sh_act[m] || sh_c2[k] >= C2_SURV) continue;

            const float* srow = S + ((size_t)b * M_ + m) * DSLOT;
            float n = 0.f;
            for (int dd = 0; dd < DSLOT; dd++) { float x = srow[dd]; n += x * x; }
            float invs = 1.f / fmaxf(sqrtf(n), 1e-12f);
            float x0 = XY[(b * M_ + m) * 2 + 0];
            float x1 = XY[(b * M_ + m) * 2 + 1];
            float invx = XYW_ / fmaxf(sqrtf(x0 * x0 + x1 * x1), 1e-12f);

            const float* cc = cen + (size_t)(c * KP_ + k) * D_;
            float dot = 0.f, f2 = 0.f;
            for (int dd = 0; dd < DSLOT; dd++) {
                float fv = srow[dd] * invs;
                dot += fv * cc[dd]; f2 += fv * fv;
            }
            float fx0 = x0 * invx, fx1 = x1 * invx;
            dot += fx0 * cc[DSLOT] + fx1 * cc[DSLOT + 1];
            f2  += fx0 * fx0 + fx1 * fx1;

            float dist2 = f2 + sh_c2[k] - 2.f * dot;
            acc += expf(-BETA_ * dist2) * sh_w[k];
        }
        atomicAdd(&sh_score, acc);
        __syncthreads();
        if (tid == 0)
            out[b * C_ + c] = alpha * base[b * C_ + c]
                            + (1.f - alpha) * sh_score / (float)sh_k;
        __syncthreads();
    }
}

extern "C" void kernel_launch(void* const* d_in, const int* in_sizes, int n_in,
                              void* d_out, int out_size)
{
    const float* base = (const float*)d_in[0];  // (B, C)
    const float* S    = (const float*)d_in[1];  // (B, M, 126)
    const float* XY   = (const float*)d_in[2];  // (B, M, 2)
    const float* P    = (const float*)d_in[3];  // (B, M)
    const float* mask = (const float*)d_in[4];  // (B, M)
    const float* cen  = (const float*)d_in[5];  // (C, K, 128)
    const float* psi  = (const float*)d_in[6];  // (C, K)
    const float* ap   = (const float*)d_in[7];  // scalar
    float* out = (float*)d_out;                 // (B, C) float32

    k_fused<<<C_, NT>>>(base, S, XY, P, mask, cen, psi, ap, out);
}

// round 6
// speedup vs baseline: 1.0337x; 1.0337x over previous
#include <cuda_runtime.h>
#include <math.h>

#define B_    256
#define M_    64
#define DSLOT 126
#define D_    128
#define C_    62
#define KP_   32
#define BETA_ 4.0f
#define XYW_  0.5f
#define TOPP_ 0.9f

// A column (c,k) can contribute a nonzero fp32 sim only if exp(-4*dist2) >= 2^-149,
// i.e. dist2 < 26. Since dist2 >= (||c||-||f||)^2 and ||f|| <= sqrt(1.25)+eps < 1.13,
// ||c||^2 >= 40 gives (6.324-1.13)^2 = 26.98 > 26 -> sim == 0.0f exactly for every
// (b,m), identical to the fp32 reference. If no column of class c survives,
// scores[:,c] == 0 exactly and out[:,c] = alpha*base[:,c].
#define C2_SURV 40.0f

#define NT 256   // == B_ : thread tid handles row b = tid on the fast path

__global__ __launch_bounds__(NT)
void k_fused(const float* __restrict__ base, const float* __restrict__ S,
             const float* __restrict__ XY, const float* __restrict__ P,
             const float* __restrict__ mask, const float* __restrict__ cen,
             const float* __restrict__ psi, const float* __restrict__ ap,
             float* __restrict__ out)
{
    const int c    = blockIdx.x;           // one block per class
    const int tid  = threadIdx.x;
    const int warp = tid >> 5;             // 0..7
    const int lane = tid & 31;

    __shared__ float sh_c2[KP_];

    // ---- front-batched loads: base row + alpha overlap the centers epoch ----
    const float my_base = base[tid * C_ + c];           // b = tid (NT == B_)
    const float ap0 = ap[0];

    // ||center||^2: warp w owns columns 4w..4w+3; 8 lanes per column,
    // 4 consecutive LDG.128 per lane (float4 index (lane&7) + 8*i).
    {
        const int   col  = warp * 4 + (lane >> 3);
        const int   sub  = lane & 7;
        const float4* cp = (const float4*)(cen + (size_t)(c * KP_ + col) * D_);
        float4 v0 = cp[sub +  0];
        float4 v1 = cp[sub +  8];
        float4 v2 = cp[sub + 16];
        float4 v3 = cp[sub + 24];
        float s = v0.x*v0.x + v0.y*v0.y + v0.z*v0.z + v0.w*v0.w
                + v1.x*v1.x + v1.y*v1.y + v1.z*v1.z + v1.w*v1.w
                + v2.x*v2.x + v2.y*v2.y + v2.z*v2.z + v2.w*v2.w
                + v3.x*v3.x + v3.y*v3.y + v3.z*v3.z + v3.w*v3.w;
        // reduce within each aligned 8-lane group
        s += __shfl_xor_sync(0xffffffffu, s, 4);
        s += __shfl_xor_sync(0xffffffffu, s, 2);
        s += __shfl_xor_sync(0xffffffffu, s, 1);
        if (sub == 0) sh_c2[col] = s;
    }
    __syncthreads();

    // block-wide verdict: every warp ballots over all 32 column norms
    const bool surv = __ballot_sync(0xffffffffu, sh_c2[lane] < C2_SURV) != 0u;
    const float alpha = 1.f / (1.f + expf(-ap0));

    if (!surv) {
        // Fast path: every sim term for class c underflows to exactly 0.0f.
        out[tid * C_ + c] = alpha * my_base;
        return;
    }

    // ---------------- survivor fallback (correct; normally never taken) ----------------
    __shared__ float sh_w[KP_];          // softmax(psi[c,:])
    __shared__ float sh_v[M_], sh_vs[M_];
    __shared__ unsigned char sh_act[M_];
    __shared__ int   sh_k;
    __shared__ float sh_score;

    if (tid == 0) {
        float mx = -1e30f;
        #pragma unroll
        for (int k = 0; k < KP_; k++) mx = fmaxf(mx, psi[c * KP_ + k]);
        float e[KP_], ssum = 0.f;
        #pragma unroll
        for (int k = 0; k < KP_; k++) { e[k] = expf(psi[c * KP_ + k] - mx); ssum += e[k]; }
        float inv = 1.f / ssum;
        #pragma unroll
        for (int k = 0; k < KP_; k++) sh_w[k] = e[k] * inv;
    }
    __syncthreads();

    for (int b = 0; b < B_; b++) {
        // --- top-p: k and active set for batch b (threads 0..63) ---
        if (tid < M_) {
            int m = tid;
            sh_v[m] = P[b * M_ + m] * mask[b * M_ + m];
        }
        __syncthreads();
        if (tid < M_) {
            int m = tid;
            float val = sh_v[m];
            int rank = 0; float tot = 0.f;
            #pragma unroll
            for (int j = 0; j < M_; j++) {
                float o = sh_v[j];
                tot += o;
                if (o > val || (o == val && j < m)) rank++;   // stable descending
            }
            sh_vs[rank] = val;
            __syncthreads();
            if (m == 0) {
                float thr = TOPP_ * (tot + 1e-8f);
                float cs = 0.f; int kk = 0;
                #pragma unroll
                for (int j = 0; j < M_; j++) { cs += sh_vs[j]; if (cs <= thr) kk++; }
                if (kk < 1) kk = 1;
                sh_k = kk;
                sh_score = 0.f;
            }
            __syncthreads();
            sh_act[m] = (rank < sh_k) ? 1 : 0;
        } else {
            __syncthreads();  // match the __syncthreads inside the tid<M_ branch
            __syncthreads();
        }
        __syncthreads();

        // --- accumulate sum over (active m) x (surviving cols) of sim * w ---
        float acc = 0.f;
        for (int pr = tid; pr < M_ * KP_; pr += NT) {
            int m = pr >> 5;
            int k = pr & 31;
            if (!sh_act[m] || sh_c2[k] >= C2_SURV) continue;

            const float* srow = S + ((size_t)b * M_ + m) * DSLOT;
            float n = 0.f;
            for (int dd = 0; dd < DSLOT; dd++) { float x = srow[dd]; n += x * x; }
            float invs = 1.f / fmaxf(sqrtf(n), 1e-12f);
            float x0 = XY[(b * M_ + m) * 2 + 0];
            float x1 = XY[(b * M_ + m) * 2 + 1];
            float invx = XYW_ / fmaxf(sqrtf(x0 * x0 + x1 * x1), 1e-12f);

            const float* cc = cen + (size_t)(c * KP_ + k) * D_;
            float dot = 0.f, f2 = 0.f;
            for (int dd = 0; dd < DSLOT; dd++) {
                float fv = srow[dd] * invs;
                dot += fv * cc[dd]; f2 += fv * fv;
            }
            float fx0 = x0 * invx, fx1 = x1 * invx;
            dot += fx0 * cc[DSLOT] + fx1 * cc[DSLOT + 1];
            f2  += fx0 * fx0 + fx1 * fx1;

            float dist2 = f2 + sh_c2[k] - 2.f * dot;
            acc += expf(-BETA_ * dist2) * sh_w[k];
        }
        atomicAdd(&sh_score, acc);
        __syncthreads();
        if (tid == 0)
            out[b * C_ + c] = alpha * base[b * C_ + c]
                            + (1.f - alpha) * sh_score / (float)sh_k;
        __syncthreads();
    }
}

extern "C" void kernel_launch(void* const* d_in, const int* in_sizes, int n_in,
                              void* d_out, int out_size)
{
    const float* base = (const float*)d_in[0];  // (B, C)
    const float* S    = (const float*)d_in[1];  // (B, M, 126)
    const float* XY   = (const float*)d_in[2];  // (B, M, 2)
    const float* P    = (const float*)d_in[3];  // (B, M)
    const float* mask = (const float*)d_in[4];  // (B, M)
    const float* cen  = (const float*)d_in[5];  // (C, K, 128)
    const float* psi  = (const float*)d_in[6];  // (C, K)
    const float* ap   = (const float*)d_in[7];  // scalar
    float* out = (float*)d_out;                 // (B, C) float32

    k_fused<<<C_, NT>>>(base, S, XY, P, mask, cen, psi, ap, out);
}

// round 7
// speedup vs baseline: 1.1082x; 1.0722x over previous
#include <cuda_runtime.h>
#include <math.h>

#define B_    256
#define M_    64
#define DSLOT 126
#define D_    128
#define C_    62
#define KP_   32
#define BETA_ 4.0f
#define XYW_  0.5f
#define TOPP_ 0.9f

// A column (c,k) can contribute a nonzero fp32 sim only if exp(-4*dist2) >= 2^-149,
// i.e. dist2 < 26. Since dist2 >= (||c||-||f||)^2 and ||f|| <= sqrt(1.25)+eps < 1.13,
// ||c||^2 >= 40 gives (6.324-1.13)^2 = 26.98 > 26 -> sim == 0.0f exactly for every
// (b,m), identical to the fp32 reference. If no column of class c survives,
// scores[:,c] == 0 exactly and out[:,c] = alpha*base[:,c].
#define C2_SURV 40.0f

#define NT 256   // == B_ : thread tid handles row b = tid on the fast path

__global__ __launch_bounds__(NT)
void k_fused(const float* __restrict__ base, const float* __restrict__ S,
             const float* __restrict__ XY, const float* __restrict__ P,
             const float* __restrict__ mask, const float* __restrict__ cen,
             const float* __restrict__ psi, const float* __restrict__ ap,
             float* __restrict__ out)
{
    const int c    = blockIdx.x;           // one block per class
    const int tid  = threadIdx.x;
    const int warp = tid >> 5;             // 0..7
    const int lane = tid & 31;

    __shared__ float sh_c2[KP_];

    // ---- front-batched loads: base row + alpha overlap the centers epoch ----
    const float my_base = base[tid * C_ + c];           // b = tid (NT == B_)
    const float ap0 = ap[0];

    // ||center||^2: warp w owns columns 4w..4w+3; 8 lanes per column,
    // 4 consecutive LDG.128 per lane (float4 index (lane&7) + 8*i).
    {
        const int   col  = warp * 4 + (lane >> 3);
        const int   sub  = lane & 7;
        const float4* cp = (const float4*)(cen + (size_t)(c * KP_ + col) * D_);
        float4 v0 = cp[sub +  0];
        float4 v1 = cp[sub +  8];
        float4 v2 = cp[sub + 16];
        float4 v3 = cp[sub + 24];
        float s = v0.x*v0.x + v0.y*v0.y + v0.z*v0.z + v0.w*v0.w
                + v1.x*v1.x + v1.y*v1.y + v1.z*v1.z + v1.w*v1.w
                + v2.x*v2.x + v2.y*v2.y + v2.z*v2.z + v2.w*v2.w
                + v3.x*v3.x + v3.y*v3.y + v3.z*v3.z + v3.w*v3.w;
        // reduce within each aligned 8-lane group
        s += __shfl_xor_sync(0xffffffffu, s, 4);
        s += __shfl_xor_sync(0xffffffffu, s, 2);
        s += __shfl_xor_sync(0xffffffffu, s, 1);
        if (sub == 0) sh_c2[col] = s;
    }
    __syncthreads();

    // block-wide verdict: every warp ballots over all 32 column norms
    const bool surv = __ballot_sync(0xffffffffu, sh_c2[lane] < C2_SURV) != 0u;
    const float alpha = 1.f / (1.f + expf(-ap0));

    if (!surv) {
        // Fast path: every sim term for class c underflows to exactly 0.0f.
        out[tid * C_ + c] = alpha * my_base;
        return;
    }

    // ---------------- survivor fallback (correct; normally never taken) ----------------
    __shared__ float sh_w[KP_];          // softmax(psi[c,:])
    __shared__ float sh_v[M_], sh_vs[M_];
    __shared__ unsigned char sh_act[M_];
    __shared__ int   sh_k;
    __shared__ float sh_score;

    if (tid == 0) {
        float mx = -1e30f;
        #pragma unroll
        for (int k = 0; k < KP_; k++) mx = fmaxf(mx, psi[c * KP_ + k]);
        float e[KP_], ssum = 0.f;
        #pragma unroll
        for (int k = 0; k < KP_; k++) { e[k] = expf(psi[c * KP_ + k] - mx); ssum += e[k]; }
        float inv = 1.f / ssum;
        #pragma unroll
        for (int k = 0; k < KP_; k++) sh_w[k] = e[k] * inv;
    }
    __syncthreads();

    for (int b = 0; b < B_; b++) {
        // --- top-p: k and active set for batch b (threads 0..63) ---
        if (tid < M_) {
            int m = tid;
            sh_v[m] = P[b * M_ + m] * mask[b * M_ + m];
        }
        __syncthreads();
        if (tid < M_) {
            int m = tid;
            float val = sh_v[m];
            int rank = 0; float tot = 0.f;
            #pragma unroll
            for (int j = 0; j < M_; j++) {
                float o = sh_v[j];
                tot += o;
                if (o > val || (o == val && j < m)) rank++;   // stable descending
            }
            sh_vs[rank] = val;
            __syncthreads();
            if (m == 0) {
                float thr = TOPP_ * (tot + 1e-8f);
                float cs = 0.f; int kk = 0;
                #pragma unroll
                for (int j = 0; j < M_; j++) { cs += sh_vs[j]; if (cs <= thr) kk++; }
                if (kk < 1) kk = 1;
                sh_k = kk;
                sh_score = 0.f;
            }
            __syncthreads();
            sh_act[m] = (rank < sh_k) ? 1 : 0;
        } else {
            __syncthreads();  // match the __syncthreads inside the tid<M_ branch
            __syncthreads();
        }
        __syncthreads();

        // --- accumulate sum over (active m) x (surviving cols) of sim * w ---
        float acc = 0.f;
        for (int pr = tid; pr < M_ * KP_; pr += NT) {
            int m = pr >> 5;
            int k = pr & 31;
            if (!sh_act[m] || sh_c2[k] >= C2_SURV) continue;

            const float* srow = S + ((size_t)b * M_ + m) * DSLOT;
            float n = 0.f;
            for (int dd = 0; dd < DSLOT; dd++) { float x = srow[dd]; n += x * x; }
            float invs = 1.f / fmaxf(sqrtf(n), 1e-12f);
            float x0 = XY[(b * M_ + m) * 2 + 0];
            float x1 = XY[(b * M_ + m) * 2 + 1];
            float invx = XYW_ / fmaxf(sqrtf(x0 * x0 + x1 * x1), 1e-12f);

            const float* cc = cen + (size_t)(c * KP_ + k) * D_;
            float dot = 0.f, f2 = 0.f;
            for (int dd = 0; dd < DSLOT; dd++) {
                float fv = srow[dd] * invs;
                dot += fv * cc[dd]; f2 += fv * fv;
            }
            float fx0 = x0 * invx, fx1 = x1 * invx;
            dot += fx0 * cc[DSLOT] + fx1 * cc[DSLOT + 1];
            f2  += fx0 * fx0 + fx1 * fx1;

            float dist2 = f2 + sh_c2[k] - 2.f * dot;
            acc += expf(-BETA_ * dist2) * sh_w[k];
        }
        atomicAdd(&sh_score, acc);
        __syncthreads();
        if (tid == 0)
            out[b * C_ + c] = alpha * base[b * C_ + c]
                            + (1.f - alpha) * sh_score / (float)sh_k;
        __syncthreads();
    }
}

extern "C" void kernel_launch(void* const* d_in, const int* in_sizes, int n_in,
                              void* d_out, int out_size)
{
    const float* base = (const float*)d_in[0];  // (B, C)
    const float* S    = (const float*)d_in[1];  // (B, M, 126)
    const float* XY   = (const float*)d_in[2];  // (B, M, 2)
    const float* P    = (const float*)d_in[3];  // (B, M)
    const float* mask = (const float*)d_in[4];  // (B, M)
    const float* cen  = (const float*)d_in[5];  // (C, K, 128)
    const float* psi  = (const float*)d_in[6];  // (C, K)
    const float* ap   = (const float*)d_in[7];  // scalar
    float* out = (float*)d_out;                 // (B, C) float32

    k_fused<<<C_, NT>>>(base, S, XY, P, mask, cen, psi, ap, out);
}